// round 5
// baseline (speedup 1.0000x reference)
#include <cuda_runtime.h>

// Problem constants (fixed for this instance)
#define HW_   262144          // H*W = 512*512
#define D_    32
#define B_    8
#define C_    19
#define N_    2097152         // B*H*W
#define NGRP_ 65536           // N / 32
#define EPS_  1e-8f

// ---------------- scratch (device globals; no allocation allowed) ----------
__device__ float g_sumv[C_ * D_];    // per-class sums of x
__device__ float g_sumn[C_ * D_];    // per-class sums of x/||x||
__device__ float g_cnt[C_];          // per-class counts
__device__ int   g_is64;             // targets dtype flag

// ---------------- K0: zero scratch + detect target dtype -------------------
__global__ void k_zero(const void* __restrict__ tgt) {
    int i = threadIdx.x;
    if (i < C_ * D_) { g_sumv[i] = 0.f; g_sumn[i] = 0.f; }
    if (i < C_) g_cnt[i] = 0.f;
    if (i == 639) {
        // int64 labels in [0,19): every odd 32-bit word is 0.
        const unsigned* w = (const unsigned*)tgt;
        int is64 = 1;
        #pragma unroll
        for (int k = 0; k < 16; k++)
            if (w[2 * k + 1] != 0u) is64 = 0;
        g_is64 = is64;
    }
}

// ---------------- K1: fused segment sums, distinct-class aggregated ---------
// lane = pixel for loads (coalesced), transpose via padded smem tile,
// lane = dim for the accumulator phase. One float2 RMW per DISTINCT class
// per 32-pixel group (E[distinct] ~ 15.6 of 32): halves RMW crossbar bytes
// and removes all same-address RAW chains within a group.
#define K1_BLOCKS 740
#define K1_WARPS  4

__global__ void __launch_bounds__(128) k_fused(const float* __restrict__ in,
                                               const void* __restrict__ tgt) {
    __shared__ float2 acc[K1_WARPS][C_ * D_];     // (.x = sum, .y = nsum)
    __shared__ float  tile[K1_WARPS][D_ * 33];    // pitch-33: conflict-free
    __shared__ float  cnt[K1_WARPS][C_];

    const int w    = threadIdx.x >> 5;
    const int lane = threadIdx.x & 31;
    const int is64 = g_is64;
    const unsigned FULL = 0xffffffffu;

    for (int i = lane; i < C_ * D_; i += 32) acc[w][i] = make_float2(0.f, 0.f);
    if (lane < C_) cnt[w][lane] = 0.f;
    __syncwarp();

    const long long* t64 = (const long long*)tgt;
    const int*       t32 = (const int*)tgt;

    const int gw     = blockIdx.x * K1_WARPS + w;
    const int nwarps = K1_BLOCKS * K1_WARPS;
    float*  tw = tile[w];
    float2* aw = acc[w];

    for (int g = gw; g < NGRP_; g += nwarps) {
        const int p0 = g * 32;
        const int p  = p0 + lane;                 // this lane's pixel
        const int b  = p0 >> 18;
        const int hw = (p0 & (HW_ - 1)) + lane;
        const float* bp = in + (size_t)b * ((size_t)D_ * HW_) + hw;

        int lab = is64 ? (int)t64[p] : t32[p];

        // coalesced: per instruction, 32 lanes cover one 128B line
        float v[D_];
        float ss = 0.f;
        #pragma unroll
        for (int d = 0; d < D_; ++d) {
            v[d] = bp[(size_t)d * HW_];
            ss += v[d] * v[d];
        }
        float r = rsqrtf(fmaxf(ss, 1e-24f));      // 1/||x||

        // class bookkeeping (lane = pixel)
        unsigned m = __match_any_sync(FULL, lab); // members of my class
        int lead   = __ffs(m) - 1;
        unsigned L = __ballot_sync(FULL, lead == lane);   // leader mask
        // pack r (clear 5 low mantissa bits, rel err ~4e-6) + 5-bit label
        unsigned pk = (__float_as_uint(r) & ~31u) | (unsigned)lab;
        if (lead == lane) cnt[w][lab] += (float)__popc(m);

        // transpose: tile[d][pixel], conflict-free both ways
        #pragma unroll
        for (int d = 0; d < D_; ++d) tw[d * 33 + lane] = v[d];
        __syncwarp();

        // accumulator phase (lane = dim); uniform control flow
        unsigned Lr = L;
        while (Lr) {
            int j = __ffs(Lr) - 1; Lr &= Lr - 1;
            unsigned mem = __shfl_sync(FULL, m, j);
            int      c   = __shfl_sync(FULL, (int)pk, j) & 31;
            float sv = 0.f, sn = 0.f;
            unsigned t = mem;
            do {
                int jj = __ffs(t) - 1; t &= t - 1;
                unsigned pj = __shfl_sync(FULL, pk, jj);
                float val = tw[lane * 33 + jj];
                float rj  = __uint_as_float(pj & ~31u);
                sv += val;
                sn = fmaf(val, rj, sn);
            } while (t);
            float2 a = aw[c * 32 + lane];
            a.x += sv;
            a.y += sn;
            aw[c * 32 + lane] = a;
        }
        __syncwarp();                             // tile reuse barrier
    }

    __syncthreads();
    for (int i = threadIdx.x; i < C_ * D_; i += 128) {
        float sx = 0.f, sy = 0.f;
        #pragma unroll
        for (int w2 = 0; w2 < K1_WARPS; ++w2) {
            float2 a = acc[w2][i];
            sx += a.x; sy += a.y;
        }
        atomicAdd(&g_sumv[i], sx);
        atomicAdd(&g_sumn[i], sy);
    }
    if (threadIdx.x < C_) {
        float s = 0.f;
        #pragma unroll
        for (int w2 = 0; w2 < K1_WARPS; ++w2) s += cnt[w2][threadIdx.x];
        atomicAdd(&g_cnt[threadIdx.x], s);
    }
}

// ---------------- K2: finalize (centers, seg_cos, sim + diff) ---------------
// 1 block, 608 threads = 19 warps, warp == class.
__global__ void k_final(float* __restrict__ out) {
    __shared__ float cs[C_ * 33];    // centers, pitch 33
    __shared__ float cn[C_];         // center norms
    __shared__ float per_class[C_];

    const int t = threadIdx.x;
    const int c = t >> 5;
    const int d = t & 31;
    const int i = c * 32 + d;

    float count = g_cnt[c];
    float denom = fmaxf(count, 1.f);
    float ctr   = g_sumv[i] / denom;
    cs[c * 33 + d] = ctr;

    float s = ctr * ctr;
    #pragma unroll
    for (int o = 16; o; o >>= 1) s += __shfl_xor_sync(0xffffffffu, s, o);
    float cnorm = sqrtf(s);
    if (d == 0) cn[c] = cnorm;

    // seg_cos_c = dot(sum_p x_p/||x_p||, center_c) / ||center_c||
    float sc = g_sumn[i] * ctr;
    #pragma unroll
    for (int o = 16; o; o >>= 1) sc += __shfl_xor_sync(0xffffffffu, sc, o);
    float segcos = sc / fmaxf(cnorm, 1e-30f);

    __syncthreads();

    // diff row c of the 19x19 center-cosine matrix
    float ci = cs[c * 33 + d];
    float accd = 0.f;
    for (int j = 0; j < C_; ++j) {
        float dot = ci * cs[j * 33 + d];
        #pragma unroll
        for (int o = 16; o; o >>= 1) dot += __shfl_xor_sync(0xffffffffu, dot, o);
        float cosv = dot / fmaxf(cnorm * cn[j], EPS_);
        accd += (j == c) ? (1.f - cosv) : fmaxf(cosv, 0.f);
    }

    if (d == 0) {
        bool present = count > 0.f;
        float sim  = present ? (1.f - segcos / denom) : 0.f;
        float diff = present ? (accd / (float)C_) : 0.f;
        per_class[c] = sim + diff;
    }
    __syncthreads();

    if (t < 32) {
        float tot = (t < C_) ? per_class[t] : 0.f;
        #pragma unroll
        for (int o = 16; o; o >>= 1) tot += __shfl_xor_sync(0xffffffffu, tot, o);
        if (t == 0) out[0] = tot;
    }
}

// ---------------- launcher --------------------------------------------------
extern "C" void kernel_launch(void* const* d_in, const int* in_sizes, int n_in,
                              void* d_out, int out_size) {
    (void)in_sizes; (void)n_in; (void)out_size;
    const float* in  = (const float*)d_in[0];
    const void*  tgt = d_in[1];
    float*       out = (float*)d_out;

    k_zero<<<1, 640>>>(tgt);
    k_fused<<<K1_BLOCKS, 128>>>(in, tgt);
    k_final<<<1, 608>>>(out);
}

// round 6
// speedup vs baseline: 1.4225x; 1.4225x over previous
#include <cuda_runtime.h>

// Problem constants (fixed for this instance)
#define HW_   262144          // H*W = 512*512
#define D_    32
#define B_    8
#define C_    19
#define N_    2097152         // B*H*W
#define TILE_ 256
#define NT_   8192            // N / TILE_
#define GRID_ 592             // 4 blocks/SM * 148
#define EPS_  1e-8f

// ---------------- scratch (zero-initialized device globals) -----------------
// k_final re-zeroes these after reading, so every graph replay starts clean.
__device__ float g_sumv[C_ * D_];    // per-class sums of x
__device__ float g_sumn[C_ * D_];    // per-class sums of x/||x||
__device__ float g_cnt[C_];          // per-class counts

// ---------------- K1: counting-sort tiles, register class accumulators ------
__global__ void __launch_bounds__(256, 4)
k_fused(const float* __restrict__ in, const void* __restrict__ tgt) {
    __shared__ float bucket[TILE_ * 33];   // slot-major, pitch 33 words
    __shared__ int   scount[C_];
    __shared__ int   sbase[C_];
    __shared__ int   s_is64;

    const int t    = threadIdx.x;
    const int w    = t >> 5;
    const int lane = t & 31;
    const unsigned FULL = 0xffffffffu;

    if (t == 0) {
        // int64 labels in [0,19): every odd 32-bit word is 0.
        const unsigned* wd = (const unsigned*)tgt;
        int is64 = 1;
        #pragma unroll
        for (int k = 0; k < 16; k++)
            if (wd[2 * k + 1] != 0u) is64 = 0;
        s_is64 = is64;
    }
    __syncthreads();
    const int is64 = s_is64;
    const long long* t64 = (const long long*)tgt;
    const int*       t32 = (const int*)tgt;

    // register accumulators: warp w owns classes w, w+8, w+16
    float sv[3] = {0.f, 0.f, 0.f};
    float sn[3] = {0.f, 0.f, 0.f};
    float cr[3] = {0.f, 0.f, 0.f};

    for (int tile = blockIdx.x; tile < NT_; tile += GRID_) {
        const int p  = tile * TILE_ + t;          // this thread's pixel
        const int b  = p >> 18;
        const int hw = p & (HW_ - 1);
        const float* bp = in + (size_t)b * ((size_t)D_ * HW_) + hw;

        // coalesced: per d, 32 lanes cover one 128B line
        float v[D_];
        float ss = 0.f;
        #pragma unroll
        for (int d = 0; d < D_; ++d) {
            v[d] = bp[(size_t)d * HW_];
            ss = fmaf(v[d], v[d], ss);
        }
        float r = rsqrtf(fmaxf(ss, 1e-24f));      // 1/||x||
        int lab = is64 ? (int)t64[p] : t32[p];

        if (t < C_) scount[t] = 0;
        __syncthreads();

        // histogram + within-class rank
        unsigned m  = __match_any_sync(FULL, lab);
        int lead    = __ffs(m) - 1;
        int rank    = __popc(m & ((1u << lane) - 1u));
        int wofs    = 0;
        if (lane == lead) wofs = atomicAdd(&scount[lab], __popc(m));
        wofs = __shfl_sync(FULL, wofs, lead);
        __syncthreads();

        // exclusive prefix scan of 19 counts (warp 0)
        if (w == 0) {
            int cv = (lane < C_) ? scount[lane] : 0;
            int sc = cv;
            #pragma unroll
            for (int o = 1; o < 32; o <<= 1) {
                int n = __shfl_up_sync(FULL, sc, o);
                if (lane >= o) sc += n;
            }
            if (lane < C_) sbase[lane] = sc - cv;
        }
        __syncthreads();

        // scatter pixel vector + r into class-sorted bucket
        const int slot = sbase[lab] + wofs + rank;
        float* bs = &bucket[slot * 33];
        #pragma unroll
        for (int d = 0; d < D_; ++d) bs[d] = v[d];
        bs[32] = r;
        __syncthreads();

        // gather: register accumulation per owned class (lane = dim)
        #pragma unroll
        for (int i = 0; i < 3; ++i) {
            const int c = w + 8 * i;
            if (c < C_) {
                const int bse = sbase[c];
                const int cc  = scount[c];
                cr[i] += (float)cc;
                float s0 = 0.f, n0 = 0.f, s1 = 0.f, n1 = 0.f;
                int k = 0;
                for (; k + 1 < cc; k += 2) {
                    const float* m0 = &bucket[(bse + k) * 33];
                    const float* m1 = &bucket[(bse + k + 1) * 33];
                    float a0 = m0[lane], r0 = m0[32];
                    float a1 = m1[lane], r1 = m1[32];
                    s0 += a0; n0 = fmaf(a0, r0, n0);
                    s1 += a1; n1 = fmaf(a1, r1, n1);
                }
                if (k < cc) {
                    const float* m0 = &bucket[(bse + k) * 33];
                    float a0 = m0[lane], r0 = m0[32];
                    s0 += a0; n0 = fmaf(a0, r0, n0);
                }
                sv[i] += s0 + s1;
                sn[i] += n0 + n1;
            }
        }
        __syncthreads();                           // bucket reuse barrier
    }

    // flush per-block class totals
    #pragma unroll
    for (int i = 0; i < 3; ++i) {
        const int c = w + 8 * i;
        if (c < C_) {
            atomicAdd(&g_sumv[c * 32 + lane], sv[i]);
            atomicAdd(&g_sumn[c * 32 + lane], sn[i]);
            if (lane == 0) atomicAdd(&g_cnt[c], cr[i]);
        }
    }
}

// ---------------- K2: finalize (centers, seg_cos, sim + diff) ---------------
// 1 block, 608 threads = 19 warps, warp == class. Re-zeroes scratch.
__global__ void k_final(float* __restrict__ out) {
    __shared__ float cs[C_ * 33];    // centers, pitch 33
    __shared__ float cn[C_];         // center norms
    __shared__ float per_class[C_];

    const int t = threadIdx.x;
    const int c = t >> 5;
    const int d = t & 31;
    const int i = c * 32 + d;

    float count = g_cnt[c];
    float denom = fmaxf(count, 1.f);
    float ctr   = g_sumv[i] / denom;
    float nsum  = g_sumn[i];
    cs[c * 33 + d] = ctr;

    // re-zero scratch for the next graph replay (each element read above by
    // exactly this thread/warp; program order within the warp makes it safe)
    g_sumv[i] = 0.f;
    g_sumn[i] = 0.f;
    if (d == 0) g_cnt[c] = 0.f;

    float s = ctr * ctr;
    #pragma unroll
    for (int o = 16; o; o >>= 1) s += __shfl_xor_sync(0xffffffffu, s, o);
    float cnorm = sqrtf(s);
    if (d == 0) cn[c] = cnorm;

    // seg_cos_c = dot(sum_p x_p/||x_p||, center_c) / ||center_c||
    float sc = nsum * ctr;
    #pragma unroll
    for (int o = 16; o; o >>= 1) sc += __shfl_xor_sync(0xffffffffu, sc, o);
    float segcos = sc / fmaxf(cnorm, 1e-30f);

    __syncthreads();

    // diff row c of the 19x19 center-cosine matrix
    float ci = cs[c * 33 + d];
    float accd = 0.f;
    for (int j = 0; j < C_; ++j) {
        float dot = ci * cs[j * 33 + d];
        #pragma unroll
        for (int o = 16; o; o >>= 1) dot += __shfl_xor_sync(0xffffffffu, dot, o);
        float cosv = dot / fmaxf(cnorm * cn[j], EPS_);
        accd += (j == c) ? (1.f - cosv) : fmaxf(cosv, 0.f);
    }

    if (d == 0) {
        bool present = count > 0.f;
        float sim  = present ? (1.f - segcos / denom) : 0.f;
        float diff = present ? (accd / (float)C_) : 0.f;
        per_class[c] = sim + diff;
    }
    __syncthreads();

    if (t < 32) {
        float tot = (t < C_) ? per_class[t] : 0.f;
        #pragma unroll
        for (int o = 16; o; o >>= 1) tot += __shfl_xor_sync(0xffffffffu, tot, o);
        if (t == 0) out[0] = tot;
    }
}

// ---------------- launcher --------------------------------------------------
extern "C" void kernel_launch(void* const* d_in, const int* in_sizes, int n_in,
                              void* d_out, int out_size) {
    (void)in_sizes; (void)n_in; (void)out_size;
    const float* in  = (const float*)d_in[0];
    const void*  tgt = d_in[1];
    float*       out = (float*)d_out;

    k_fused<<<GRID_, 256>>>(in, tgt);
    k_final<<<1, 608>>>(out);
}

// round 10
// speedup vs baseline: 1.4275x; 1.0035x over previous
#include <cuda_runtime.h>

// Problem constants (fixed for this instance)
#define HW_   262144          // H*W = 512*512
#define D_    32
#define B_    8
#define C_    19
#define N_    2097152         // B*H*W
#define TILE_ 256
#define NT_   8192            // N / TILE_
#define GRID_ 592             // 4 blocks/SM * 148
#define PITCH 34              // bucket row pitch (floats): 8B-aligned, gather conflict-free
#define EPS_  1e-8f

// ---------------- scratch (zero-initialized device globals) -----------------
// k_final re-zeroes/resets these after reading, so every replay starts clean.
__device__ float    g_sumv[C_ * D_];   // per-class sums of x
__device__ float    g_sumn[C_ * D_];   // per-class sums of x/||x||
__device__ float    g_cnt[C_];         // per-class counts
__device__ unsigned g_tile;            // dynamic work counter

// ---------------- K1: counting-sort tiles, register class accumulators ------
__global__ void __launch_bounds__(256, 4)
k_fused(const float* __restrict__ in, const void* __restrict__ tgt) {
    __shared__ float bucket[TILE_ * PITCH];  // slot-major
    __shared__ int   scount[C_];
    __shared__ int   s_next;
    __shared__ int   s_is64;

    const int t    = threadIdx.x;
    const int w    = t >> 5;
    const int lane = t & 31;
    const unsigned FULL = 0xffffffffu;

    if (t == 0) {
        // int64 labels in [0,19): every odd 32-bit word is 0.
        const unsigned* wd = (const unsigned*)tgt;
        int is64 = 1;
        #pragma unroll
        for (int k = 0; k < 16; k++)
            if (wd[2 * k + 1] != 0u) is64 = 0;
        s_is64 = is64;
    }
    __syncthreads();
    const int is64 = s_is64;
    const long long* t64 = (const long long*)tgt;
    const int*       t32 = (const int*)tgt;

    // register accumulators: warp w owns classes w, w+8, w+16
    float sv[3] = {0.f, 0.f, 0.f};
    float sn[3] = {0.f, 0.f, 0.f};
    float cr[3] = {0.f, 0.f, 0.f};

    for (;;) {
        // fetch next tile + zero histogram (prev gather finished: loop-end sync)
        if (t == 0) s_next = (int)atomicAdd(&g_tile, 1u);
        if (t < C_) scount[t] = 0;
        __syncthreads();
        const int tile = s_next;
        if (tile >= NT_) break;

        const int p  = tile * TILE_ + t;          // this thread's pixel
        const int b  = p >> 18;
        const int hw = p & (HW_ - 1);
        const float* bp = in + (size_t)b * ((size_t)D_ * HW_) + hw;

        // coalesced: per d, 32 lanes cover one 128B line
        float v[D_];
        float ss = 0.f;
        #pragma unroll
        for (int d = 0; d < D_; ++d) {
            v[d] = bp[(size_t)d * HW_];
            ss = fmaf(v[d], v[d], ss);
        }
        float r = rsqrtf(fmaxf(ss, 1e-24f));      // 1/||x||
        int lab = is64 ? (int)t64[p] : t32[p];

        // histogram + within-class rank
        unsigned m  = __match_any_sync(FULL, lab);
        int lead    = __ffs(m) - 1;
        int rank    = __popc(m & ((1u << lane) - 1u));
        int wofs    = 0;
        if (lane == lead) wofs = atomicAdd(&scount[lab], __popc(m));
        wofs = __shfl_sync(FULL, wofs, lead);
        __syncthreads();

        // redundant per-warp exclusive scan of the 19 counts (no extra sync)
        int cv = (lane < C_) ? scount[lane] : 0;
        int sc = cv;
        #pragma unroll
        for (int o = 1; o < 32; o <<= 1) {
            int nn = __shfl_up_sync(FULL, sc, o);
            if (lane >= o) sc += nn;
        }
        int mybase = __shfl_sync(FULL, sc - cv, lab);   // sbase[lab]

        // scatter pixel vector + r into class-sorted bucket (float2 STS)
        const int slot = mybase + wofs + rank;
        float2* bs2 = (float2*)&bucket[slot * PITCH];
        #pragma unroll
        for (int k = 0; k < 16; ++k)
            bs2[k] = make_float2(v[2 * k], v[2 * k + 1]);
        bucket[slot * PITCH + 32] = r;
        __syncthreads();

        // gather: register accumulation per owned class (lane = dim)
        #pragma unroll
        for (int i = 0; i < 3; ++i) {
            const int c = w + 8 * i;
            if (c < C_) {
                const int bse = __shfl_sync(FULL, sc - cv, c); // sbase[c]
                const int cc  = __shfl_sync(FULL, cv, c);      // scount[c]
                cr[i] += (float)cc;
                float s0 = 0.f, n0 = 0.f, s1 = 0.f, n1 = 0.f;
                int k = 0;
                for (; k + 1 < cc; k += 2) {
                    const float* m0 = &bucket[(bse + k) * PITCH];
                    const float* m1 = &bucket[(bse + k + 1) * PITCH];
                    float a0 = m0[lane], r0 = m0[32];
                    float a1 = m1[lane], r1 = m1[32];
                    s0 += a0; n0 = fmaf(a0, r0, n0);
                    s1 += a1; n1 = fmaf(a1, r1, n1);
                }
                if (k < cc) {
                    const float* m0 = &bucket[(bse + k) * PITCH];
                    float a0 = m0[lane], r0 = m0[32];
                    s0 += a0; n0 = fmaf(a0, r0, n0);
                }
                sv[i] += s0 + s1;
                sn[i] += n0 + n1;
            }
        }
        __syncthreads();                           // bucket reuse barrier
    }

    // flush per-block class totals
    #pragma unroll
    for (int i = 0; i < 3; ++i) {
        const int c = w + 8 * i;
        if (c < C_) {
            atomicAdd(&g_sumv[c * 32 + lane], sv[i]);
            atomicAdd(&g_sumn[c * 32 + lane], sn[i]);
            if (lane == 0) atomicAdd(&g_cnt[c], cr[i]);
        }
    }
}

// ---------------- K2: finalize (centers, seg_cos, sim + diff) ---------------
// 1 block, 608 threads. Phase 1: warp == class (19 warps). Phase 2: pairwise
// (i,j) threads for the 19x19 cosine matrix. Resets all scratch.
__global__ void k_final(float* __restrict__ out) {
    __shared__ float cs[C_ * 33];    // centers, pitch 33
    __shared__ float cn[C_];         // center norms
    __shared__ float srow[C_];       // diff row sums
    __shared__ float sim[C_];
    __shared__ float spres[C_];

    const int t = threadIdx.x;
    const int c = t >> 5;
    const int d = t & 31;
    const int i = c * 32 + d;

    float count = g_cnt[c];
    float denom = fmaxf(count, 1.f);
    float ctr   = g_sumv[i] / denom;
    float nsum  = g_sumn[i];
    cs[c * 33 + d] = ctr;

    // reset scratch for the next replay
    g_sumv[i] = 0.f;
    g_sumn[i] = 0.f;
    if (t == 0) g_tile = 0u;
    if (d == 0) { g_cnt[c] = 0.f; srow[c] = 0.f; }

    float s = ctr * ctr;
    #pragma unroll
    for (int o = 16; o; o >>= 1) s += __shfl_xor_sync(0xffffffffu, s, o);
    float cnorm = sqrtf(s);

    // seg_cos_c = dot(sum_p x_p/||x_p||, center_c) / ||center_c||
    float sc = nsum * ctr;
    #pragma unroll
    for (int o = 16; o; o >>= 1) sc += __shfl_xor_sync(0xffffffffu, sc, o);

    if (d == 0) {
        bool present = count > 0.f;
        float segcos = sc / fmaxf(cnorm, 1e-30f);
        cn[c]    = cnorm;
        sim[c]   = present ? (1.f - segcos / denom) : 0.f;
        spres[c] = present ? 1.f : 0.f;
    }
    __syncthreads();

    // pairwise diff terms: thread (i,j) for t < 361
    if (t < C_ * C_) {
        const int ii = t / C_;
        const int jj = t - ii * C_;
        float dot = 0.f;
        #pragma unroll
        for (int dd = 0; dd < D_; ++dd)
            dot = fmaf(cs[ii * 33 + dd], cs[jj * 33 + dd], dot);
        float cosv = dot / fmaxf(cn[ii] * cn[jj], EPS_);
        float term = (ii == jj) ? (1.f - cosv) : fmaxf(cosv, 0.f);
        atomicAdd(&srow[ii], term);
    }
    __syncthreads();

    if (t < 32) {
        float tot = 0.f;
        if (t < C_)
            tot = sim[t] + spres[t] * (srow[t] / (float)C_);
        #pragma unroll
        for (int o = 16; o; o >>= 1) tot += __shfl_xor_sync(0xffffffffu, tot, o);
        if (t == 0) out[0] = tot;
    }
}

// ---------------- launcher --------------------------------------------------
extern "C" void kernel_launch(void* const* d_in, const int* in_sizes, int n_in,
                              void* d_out, int out_size) {
    (void)in_sizes; (void)n_in; (void)out_size;
    const float* in  = (const float*)d_in[0];
    const void*  tgt = d_in[1];
    float*       out = (float*)d_out;

    k_fused<<<GRID_, 256>>>(in, tgt);
    k_final<<<1, 608>>>(out);
}